// round 4
// baseline (speedup 1.0000x reference)
#include <cuda_runtime.h>
#include <math.h>

#define C 64
#define TE 128
#define BT 256
#define SAS 132
#define NOUTC 32
#define NMAX 100000

// ---------------- scratch (device globals; no allocation) ----------------
__device__ float g_hA[(size_t)NMAX * C];
__device__ float g_hB[(size_t)NMAX * C];
__device__ float g_xA[(size_t)NMAX * 3];
__device__ float g_hn[(size_t)NMAX * C];
__device__ float g_xs[(size_t)NMAX * 4];

// ---------------- packed f32x2 helpers ----------------
__device__ __forceinline__ unsigned long long pk2(float x, float y) {
    unsigned long long r;
    asm("mov.b64 %0, {%1, %2};" : "=l"(r) : "f"(x), "f"(y));
    return r;
}
__device__ __forceinline__ float2 up2(unsigned long long v) {
    float lo, hi;
    asm("mov.b64 {%0, %1}, %2;" : "=f"(lo), "=f"(hi) : "l"(v));
    return make_float2(lo, hi);
}
__device__ __forceinline__ void fma2(unsigned long long& d, unsigned long long a, unsigned long long b) {
    asm("fma.rn.f32x2 %0, %1, %2, %0;" : "+l"(d) : "l"(a), "l"(b));
}
__device__ __forceinline__ float siluf(float v) {
    return v * (1.0f / (1.0f + __expf(-v)));
}

struct Acc { unsigned long long a[4][4]; };

__device__ __forceinline__ void init_bias(Acc& acc, const float* bias, int tx8) {
    const ulonglong2* b = reinterpret_cast<const ulonglong2*>(bias + tx8);
    ulonglong2 b01 = b[0], b23 = b[1];
#pragma unroll
    for (int i = 0; i < 4; i++) {
        acc.a[i][0] = b01.x; acc.a[i][1] = b01.y;
        acc.a[i][2] = b23.x; acc.a[i][3] = b23.y;
    }
}

// A is k-major [KN][tile] with row stride AS; W is [KN][WS] row-major.
// Thread computes 4 rows x 8 cols with packed f32x2 FMA.
template<int KN, int AS, int WS>
__device__ __forceinline__ void gemm_tile(const float* __restrict__ sA,
                                          const float* __restrict__ sW,
                                          int ty4, int tx8, Acc& acc) {
#pragma unroll 8
    for (int k = 0; k < KN; k++) {
        float4 av = *reinterpret_cast<const float4*>(sA + k * AS + ty4);
        const ulonglong2* bp = reinterpret_cast<const ulonglong2*>(sW + k * WS + tx8);
        ulonglong2 b01 = bp[0];
        ulonglong2 b23 = bp[1];
        unsigned long long a0 = pk2(av.x, av.x);
        fma2(acc.a[0][0], a0, b01.x); fma2(acc.a[0][1], a0, b01.y);
        fma2(acc.a[0][2], a0, b23.x); fma2(acc.a[0][3], a0, b23.y);
        unsigned long long a1 = pk2(av.y, av.y);
        fma2(acc.a[1][0], a1, b01.x); fma2(acc.a[1][1], a1, b01.y);
        fma2(acc.a[1][2], a1, b23.x); fma2(acc.a[1][3], a1, b23.y);
        unsigned long long a2 = pk2(av.z, av.z);
        fma2(acc.a[2][0], a2, b01.x); fma2(acc.a[2][1], a2, b01.y);
        fma2(acc.a[2][2], a2, b23.x); fma2(acc.a[2][3], a2, b23.y);
        unsigned long long a3 = pk2(av.w, av.w);
        fma2(acc.a[3][0], a3, b01.x); fma2(acc.a[3][1], a3, b01.y);
        fma2(acc.a[3][2], a3, b23.x); fma2(acc.a[3][3], a3, b23.y);
    }
}

__device__ __forceinline__ void unpack_acc(const Acc& acc, float r[4][8]) {
#pragma unroll
    for (int i = 0; i < 4; i++)
#pragma unroll
        for (int j = 0; j < 4; j++) {
            float2 v = up2(acc.a[i][j]);
            r[i][2*j] = v.x; r[i][2*j+1] = v.y;
        }
}

__device__ __forceinline__ void silu_r(float r[4][8]) {
#pragma unroll
    for (int i = 0; i < 4; i++)
#pragma unroll
        for (int c = 0; c < 8; c++) r[i][c] = siluf(r[i][c]);
}

// write activated tile back k-major (transposed) for next GEMM's A operand
__device__ __forceinline__ void store_t(float* __restrict__ sA, int ty4, int tx8, const float r[4][8]) {
#pragma unroll
    for (int c = 0; c < 8; c++) {
        float4 v = make_float4(r[0][c], r[1][c], r[2][c], r[3][c]);
        *reinterpret_cast<float4*>(sA + (tx8 + c) * SAS + ty4) = v;
    }
}

// ---------------- zero kernel ----------------
__global__ void zero_kernel(float* __restrict__ hn, float* __restrict__ xs, int nh, int nx) {
    int i = blockIdx.x * blockDim.x + threadIdx.x;
    int st = gridDim.x * blockDim.x;
    for (int j = i; j < nh; j += st) hn[j] = 0.0f;
    for (int j = i; j < nx; j += st) xs[j] = 0.0f;
}

// ---------------- edge kernel ----------------
// smem: W1(129x64) b1 W2(64x64) b2 CW1(64x64) cb1 cw2 | A(64x132) B(64x132) | xd(3x128) rad(128) dst(128)
#define EDGE_SMEM_FLOATS (129*C + C + C*C + C + C*C + C + C + C*SAS + C*SAS + 3*TE + TE + TE)
#define EDGE_SMEM_BYTES  (EDGE_SMEM_FLOATS * 4)

__global__ void __launch_bounds__(BT, 1) edge_kernel(
    const float* __restrict__ h, const float* __restrict__ x,
    const int* __restrict__ src, const int* __restrict__ dst,
    const float* __restrict__ ew1, const float* __restrict__ eb1,
    const float* __restrict__ ew2, const float* __restrict__ eb2,
    const float* __restrict__ cw1, const float* __restrict__ cb1,
    const float* __restrict__ cw2,
    float* __restrict__ hn, float* __restrict__ xs, int E, int do_coord)
{
    extern __shared__ float sm[];
    float* sW1  = sm;                    // rows: h_src 0..63, h_dst 64..127, radial 128
    float* sB1  = sW1 + 129*C;
    float* sW2  = sB1 + C;
    float* sB2  = sW2 + C*C;
    float* sC1  = sB2 + C;
    float* sCB1 = sC1 + C*C;
    float* sC2  = sCB1 + C;
    float* sA   = sC2 + C;               // 64 x 132 (k-major)
    float* sBf  = sA + C*SAS;            // 64 x 132 (k-major)
    float* sXd  = sBf + C*SAS;           // [3][TE]
    float* sRad = sXd + 3*TE;
    int*   sDst = (int*)(sRad + TE);

    const int tid = threadIdx.x;
    for (int i = tid; i < 129*C; i += BT) sW1[i] = ew1[i];
    for (int i = tid; i < C*C; i += BT) { sW2[i] = ew2[i]; sC1[i] = cw1[i]; }
    if (tid < C) { sB1[tid] = eb1[tid]; sB2[tid] = eb2[tid]; sCB1[tid] = cb1[tid]; sC2[tid] = cw2[tid]; }

    const int tx8 = (tid & 7) * 8;
    const int ty4 = (tid >> 3) * 4;
    const int ntiles = (E + TE - 1) / TE;

    for (int tile = blockIdx.x; tile < ntiles; tile += gridDim.x) {
        __syncthreads();
        const int e0 = tile * TE;

        // per-edge geometry
        if (tid < TE) {
            int e = e0 + tid;
            if (e < E) {
                int s = src[e], d = dst[e];
                sDst[tid] = d;
                float dx = x[3*s+0] - x[3*d+0];
                float dy = x[3*s+1] - x[3*d+1];
                float dz = x[3*s+2] - x[3*d+2];
                float r = dx*dx + dy*dy + dz*dz;
                float inv = 1.0f / (sqrtf(r) + 1e-30f);
                sRad[tid] = r;
                sXd[tid] = dx*inv; sXd[TE+tid] = dy*inv; sXd[2*TE+tid] = dz*inv;
            } else {
                sDst[tid] = -1; sRad[tid] = 0.0f;
                sXd[tid] = 0.0f; sXd[TE+tid] = 0.0f; sXd[2*TE+tid] = 0.0f;
            }
        }
        // gather h[src], h[dst] -> k-major smem
        {
            const int el = tid >> 1, half = tid & 1;
            const int e = e0 + el;
            const bool v = (e < E);
            const int srow = v ? src[e] : 0;
            const int drow = v ? dst[e] : 0;
            const float4 z4 = make_float4(0.f, 0.f, 0.f, 0.f);
#pragma unroll
            for (int i = 0; i < 8; i++) {
                int k = half*32 + i*4;
                float4 vs = v ? *reinterpret_cast<const float4*>(h + (size_t)srow*C + k) : z4;
                float4 vd = v ? *reinterpret_cast<const float4*>(h + (size_t)drow*C + k) : z4;
                sA[(k+0)*SAS+el] = vs.x; sA[(k+1)*SAS+el] = vs.y; sA[(k+2)*SAS+el] = vs.z; sA[(k+3)*SAS+el] = vs.w;
                sBf[(k+0)*SAS+el] = vd.x; sBf[(k+1)*SAS+el] = vd.y; sBf[(k+2)*SAS+el] = vd.z; sBf[(k+3)*SAS+el] = vd.w;
            }
        }
        __syncthreads();

        // GEMM1: hidden1 = silu([h_src, h_dst, radial] @ W1 + b1)
        Acc acc;
        init_bias(acc, sB1, tx8);
        {
            const ulonglong2* wr = reinterpret_cast<const ulonglong2*>(sW1 + 128*C + tx8);
            ulonglong2 w01 = wr[0], w23 = wr[1];
#pragma unroll
            for (int i = 0; i < 4; i++) {
                float rr = sRad[ty4 + i];
                unsigned long long rp = pk2(rr, rr);
                fma2(acc.a[i][0], rp, w01.x); fma2(acc.a[i][1], rp, w01.y);
                fma2(acc.a[i][2], rp, w23.x); fma2(acc.a[i][3], rp, w23.y);
            }
        }
        gemm_tile<C, SAS, C>(sA,  sW1,       ty4, tx8, acc);
        gemm_tile<C, SAS, C>(sBf, sW1 + C*C, ty4, tx8, acc);
        __syncthreads();
        float r1[4][8];
        unpack_acc(acc, r1);
        silu_r(r1);
        store_t(sA, ty4, tx8, r1);
        __syncthreads();

        // GEMM2: msg_h = silu(hidden1 @ W2 + b2)
        init_bias(acc, sB2, tx8);
        gemm_tile<C, SAS, C>(sA, sW2, ty4, tx8, acc);
        __syncthreads();
        float mh[4][8];
        unpack_acc(acc, mh);
        silu_r(mh);
        store_t(sA, ty4, tx8, mh);
        // scatter msg_h into h_neigh
#pragma unroll
        for (int i = 0; i < 4; i++) {
            int d = sDst[ty4 + i];
            if (d >= 0) {
                float* p = hn + (size_t)d*C + tx8;
#pragma unroll
                for (int c = 0; c < 8; c++) atomicAdd(p + c, mh[i][c]);
            }
        }
        __syncthreads();

        if (!do_coord) continue;

        // GEMM3: q = silu(msg_h @ CW1 + cb1); coord_s = q . cw2
        init_bias(acc, sCB1, tx8);
        gemm_tile<C, SAS, C>(sA, sC1, ty4, tx8, acc);
        float q[4][8];
        unpack_acc(acc, q);
        silu_r(q);
        float c2[8];
#pragma unroll
        for (int j = 0; j < 8; j++) c2[j] = sC2[tx8 + j];
        float csum[4];
#pragma unroll
        for (int i = 0; i < 4; i++) {
            float s = 0.f;
#pragma unroll
            for (int j = 0; j < 8; j++) s += q[i][j] * c2[j];
            csum[i] = s;
        }
#pragma unroll
        for (int m = 1; m < 8; m <<= 1) {
#pragma unroll
            for (int i = 0; i < 4; i++)
                csum[i] += __shfl_xor_sync(0xffffffffu, csum[i], m);
        }
        if ((tid & 7) == 0) {
#pragma unroll
            for (int i = 0; i < 4; i++) {
                int el = ty4 + i;
                int d = sDst[el];
                if (d >= 0) {
                    float cs = csum[i];
                    float* p = xs + (size_t)d*4;
                    atomicAdd(p + 0, cs * sXd[el]);
                    atomicAdd(p + 1, cs * sXd[TE + el]);
                    atomicAdd(p + 2, cs * sXd[2*TE + el]);
                    atomicAdd(p + 3, 1.0f);
                }
            }
        }
    }
}

// ---------------- node kernel ----------------
// smem: NW1(128x64) nb1 NW2(64x64) nb2 ln_g ln_b | A(128x132) | H(64x132)
#define NODE_SMEM_FLOATS (2*C*C + C + C*C + C + C + C + 2*C*SAS + C*SAS)
#define NODE_SMEM_BYTES  (NODE_SMEM_FLOATS * 4)

__global__ void __launch_bounds__(BT, 1) node_kernel(
    const float* __restrict__ h, const float* __restrict__ x,
    const float* __restrict__ hn, const float* __restrict__ xs,
    const float* __restrict__ nw1, const float* __restrict__ nb1,
    const float* __restrict__ nw2, const float* __restrict__ nb2,
    const float* __restrict__ lng, const float* __restrict__ lnb,
    float* __restrict__ h_out, float* __restrict__ x_out, int N, int do_x)
{
    extern __shared__ float sm[];
    float* sW1 = sm;              // 128 x 64 (rows 0..63: h, 64..127: h_neigh)
    float* sB1 = sW1 + 2*C*C;
    float* sW2 = sB1 + C;
    float* sB2 = sW2 + C*C;
    float* sLG = sB2 + C;
    float* sLB = sLG + C;
    float* sA  = sLB + C;         // 128 x 132 (k-major)
    float* sH  = sA + 2*C*SAS;    // 64 x 132 (k-major)

    const int tid = threadIdx.x;
    for (int i = tid; i < 2*C*C; i += BT) sW1[i] = nw1[i];
    for (int i = tid; i < C*C; i += BT) sW2[i] = nw2[i];
    if (tid < C) { sB1[tid] = nb1[tid]; sB2[tid] = nb2[tid]; sLG[tid] = lng[tid]; sLB[tid] = lnb[tid]; }

    const int tx8 = (tid & 7) * 8;
    const int ty4 = (tid >> 3) * 4;
    const int base = blockIdx.x * TE;

    // x update (independent of GEMM path)
    if (do_x && tid < TE) {
        int n = base + tid;
        if (n < N) {
            float4 s = *reinterpret_cast<const float4*>(xs + (size_t)n*4);
            float deg = fmaxf(s.w, 1.0f);
            x_out[3*n+0] = x[3*n+0] + s.x / deg;
            x_out[3*n+1] = x[3*n+1] + s.y / deg;
            x_out[3*n+2] = x[3*n+2] + s.z / deg;
        }
    }

    // gather [h | hn] -> k-major smem
    {
        const int el = tid >> 1, half = tid & 1;
        const int n = base + el;
        const bool v = (n < N);
        const float4 z4 = make_float4(0.f, 0.f, 0.f, 0.f);
#pragma unroll
        for (int i = 0; i < 8; i++) {
            int k = half*32 + i*4;
            float4 vh = v ? *reinterpret_cast<const float4*>(h  + (size_t)n*C + k) : z4;
            float4 vn = v ? *reinterpret_cast<const float4*>(hn + (size_t)n*C + k) : z4;
            sA[(k+0)*SAS+el] = vh.x; sA[(k+1)*SAS+el] = vh.y; sA[(k+2)*SAS+el] = vh.z; sA[(k+3)*SAS+el] = vh.w;
            sA[(C+k+0)*SAS+el] = vn.x; sA[(C+k+1)*SAS+el] = vn.y; sA[(C+k+2)*SAS+el] = vn.z; sA[(C+k+3)*SAS+el] = vn.w;
        }
    }
    __syncthreads();

    // GEMM1: hidden = silu([h, hn] @ NW1 + nb1)   K = 128
    Acc acc;
    init_bias(acc, sB1, tx8);
    gemm_tile<2*C, SAS, C>(sA, sW1, ty4, tx8, acc);
    __syncthreads();
    float r1[4][8];
    unpack_acc(acc, r1);
    silu_r(r1);
    store_t(sH, ty4, tx8, r1);
    __syncthreads();

    // GEMM2: h_new = hidden @ NW2 + nb2
    init_bias(acc, sB2, tx8);
    gemm_tile<C, SAS, C>(sH, sW2, ty4, tx8, acc);
    float r2[4][8];
    unpack_acc(acc, r2);

    // gelu (exact) then layernorm across the 8-thread col group
#pragma unroll
    for (int i = 0; i < 4; i++) {
        float s1 = 0.f, s2 = 0.f;
#pragma unroll
        for (int c = 0; c < 8; c++) {
            float v = r2[i][c];
            v = 0.5f * v * (1.0f + erff(v * 0.70710678118654752f));
            r2[i][c] = v;
            s1 += v; s2 += v*v;
        }
#pragma unroll
        for (int m = 1; m < 8; m <<= 1) {
            s1 += __shfl_xor_sync(0xffffffffu, s1, m);
            s2 += __shfl_xor_sync(0xffffffffu, s2, m);
        }
        float mu = s1 * (1.0f / C);
        float var = s2 * (1.0f / C) - mu * mu;
        float inv = rsqrtf(var + 1e-5f);
        int n = base + ty4 + i;
        if (n < N) {
            float o[8];
#pragma unroll
            for (int c = 0; c < 8; c++)
                o[c] = (r2[i][c] - mu) * inv * sLG[tx8 + c] + sLB[tx8 + c];
            float* p = h_out + (size_t)n*C + tx8;
            *reinterpret_cast<float4*>(p)     = make_float4(o[0], o[1], o[2], o[3]);
            *reinterpret_cast<float4*>(p + 4) = make_float4(o[4], o[5], o[6], o[7]);
        }
    }
}

// ---------------- output head ----------------
// tile = 256 nodes; thread = 4 nodes x 8 cols; tx spans 32 output cols.
#define OTILE 256
#define OAS 260
#define OUT_SMEM_FLOATS (C*OAS + C*NOUTC + NOUTC)
#define OUT_SMEM_BYTES  (OUT_SMEM_FLOATS * 4)

__global__ void __launch_bounds__(BT, 1) out_kernel(
    const float* __restrict__ h, const float* __restrict__ ow,
    const float* __restrict__ ob, float* __restrict__ out, int N)
{
    extern __shared__ float sm[];
    float* sA = sm;              // 64 x 260 (k-major)
    float* sW = sA + C*OAS;      // 64 x 32
    float* sB = sW + C*NOUTC;

    const int tid = threadIdx.x;
    for (int i = tid; i < C*NOUTC; i += BT) sW[i] = ow[i];
    if (tid < NOUTC) sB[tid] = ob[tid];

    const int base = blockIdx.x * OTILE;
    // stage h tile k-major
    {
        const float4* hg = reinterpret_cast<const float4*>(h + (size_t)base * C);
        const float4 z4 = make_float4(0.f, 0.f, 0.f, 0.f);
        for (int idx = tid; idx < OTILE * (C/4); idx += BT) {
            int p = idx * 4;
            int ln = p >> 6;          // local node
            int k = p & 63;
            float4 v = (base + ln < N) ? hg[idx] : z4;
            sA[(k+0)*OAS+ln] = v.x; sA[(k+1)*OAS+ln] = v.y;
            sA[(k+2)*OAS+ln] = v.z; sA[(k+3)*OAS+ln] = v.w;
        }
    }
    __syncthreads();

    const int tx8 = (tid & 3) * 8;       // 32 cols
    const int ty4 = (tid >> 2) * 4;      // 256 rows
    Acc acc;
    init_bias(acc, sB, tx8);
    gemm_tile<C, OAS, NOUTC>(sA, sW, ty4, tx8, acc);
    float r[4][8];
    unpack_acc(acc, r);
#pragma unroll
    for (int i = 0; i < 4; i++) {
        int n = base + ty4 + i;
        if (n < N) {
            float* p = out + (size_t)n * NOUTC + tx8;
            *reinterpret_cast<float4*>(p)     = make_float4(r[i][0], r[i][1], r[i][2], r[i][3]);
            *reinterpret_cast<float4*>(p + 4) = make_float4(r[i][4], r[i][5], r[i][6], r[i][7]);
        }
    }
}

// ---------------- launch ----------------
extern "C" void kernel_launch(void* const* d_in, const int* in_sizes, int n_in,
                              void* d_out, int out_size) {
    const float* node_feat = (const float*)d_in[0];
    const float* xyz = (const float*)d_in[1];
    const int* src = (const int*)d_in[2];
    const int* dst = (const int*)d_in[3];
    const float* ew1 = (const float*)d_in[4];
    const float* eb1 = (const float*)d_in[5];
    const float* ew2 = (const float*)d_in[6];
    const float* eb2 = (const float*)d_in[7];
    const float* cw1 = (const float*)d_in[8];
    const float* cb1 = (const float*)d_in[9];
    const float* cw2 = (const float*)d_in[10];
    const float* nw1 = (const float*)d_in[11];
    const float* nb1 = (const float*)d_in[12];
    const float* nw2 = (const float*)d_in[13];
    const float* nb2 = (const float*)d_in[14];
    const float* lng = (const float*)d_in[15];
    const float* lnb = (const float*)d_in[16];
    const float* ow  = (const float*)d_in[17];
    const float* ob  = (const float*)d_in[18];

    const int N = in_sizes[0] / C;
    const int E = in_sizes[2];

    float *hA, *hB, *xA, *hn, *xs;
    cudaGetSymbolAddress((void**)&hA, g_hA);
    cudaGetSymbolAddress((void**)&hB, g_hB);
    cudaGetSymbolAddress((void**)&xA, g_xA);
    cudaGetSymbolAddress((void**)&hn, g_hn);
    cudaGetSymbolAddress((void**)&xs, g_xs);

    cudaFuncSetAttribute(edge_kernel, cudaFuncAttributeMaxDynamicSharedMemorySize, EDGE_SMEM_BYTES);
    cudaFuncSetAttribute(node_kernel, cudaFuncAttributeMaxDynamicSharedMemorySize, NODE_SMEM_BYTES);
    cudaFuncSetAttribute(out_kernel,  cudaFuncAttributeMaxDynamicSharedMemorySize, OUT_SMEM_BYTES);

    const int ntiles_n = (N + TE - 1) / TE;
    const int ntiles_o = (N + OTILE - 1) / OTILE;

    // layer 0
    zero_kernel<<<512, BT>>>(hn, xs, N*C, N*4);
    edge_kernel<<<148, BT, EDGE_SMEM_BYTES>>>(node_feat, xyz, src, dst,
        ew1, eb1, ew2, eb2, cw1, cb1, cw2, hn, xs, E, 1);
    node_kernel<<<ntiles_n, BT, NODE_SMEM_BYTES>>>(node_feat, xyz, hn, xs,
        nw1, nb1, nw2, nb2, lng, lnb, hA, xA, N, 1);

    // layer 1 (x update and coord path are dead w.r.t. the output -> skipped)
    zero_kernel<<<512, BT>>>(hn, xs, N*C, N*4);
    edge_kernel<<<148, BT, EDGE_SMEM_BYTES>>>(hA, xA, src, dst,
        ew1 + 129*C, eb1 + C, ew2 + C*C, eb2 + C, cw1 + C*C, cb1 + C, cw2 + C,
        hn, xs, E, 0);
    node_kernel<<<ntiles_n, BT, NODE_SMEM_BYTES>>>(hA, xA, hn, xs,
        nw1 + 2*C*C, nb1 + C, nw2 + C*C, nb2 + C, lng, lnb, hB, xA, N, 0);

    out_kernel<<<ntiles_o, BT, OUT_SMEM_BYTES>>>(hB, ow, ob, (float*)d_out, N);
}

// round 7
// speedup vs baseline: 2.2799x; 2.2799x over previous
#include <cuda_runtime.h>
#include <math.h>

#define C 64
#define TE 128
#define BT 256
#define SAS 132
#define NOUTC 32
#define NMAX 100000

// ---------------- scratch (device globals; no allocation) ----------------
__device__ float g_hA[(size_t)NMAX * C];
__device__ float g_hB[(size_t)NMAX * C];
__device__ float g_xA[(size_t)NMAX * 3];
__device__ float g_hn[(size_t)NMAX * C];
__device__ float g_xs[(size_t)NMAX * 4];
__device__ float g_Ps[(size_t)NMAX * C];
__device__ float g_Pd[(size_t)NMAX * C];

// ---------------- helpers ----------------
__device__ __forceinline__ int swz(int row, int col) {
    return col ^ (((row >> 3) & 7) << 2);
}
__device__ __forceinline__ unsigned long long pk2(float x, float y) {
    unsigned long long r;
    asm("mov.b64 %0, {%1, %2};" : "=l"(r) : "f"(x), "f"(y));
    return r;
}
__device__ __forceinline__ float2 up2(unsigned long long v) {
    float lo, hi;
    asm("mov.b64 {%0, %1}, %2;" : "=f"(lo), "=f"(hi) : "l"(v));
    return make_float2(lo, hi);
}
__device__ __forceinline__ void fma2(unsigned long long& d, unsigned long long a, unsigned long long b) {
    asm("fma.rn.f32x2 %0, %1, %2, %0;" : "+l"(d) : "l"(a), "l"(b));
}
__device__ __forceinline__ void redv4(float* p, float a, float b, float c, float d) {
    asm volatile("red.global.add.v4.f32 [%0], {%1, %2, %3, %4};"
                 :: "l"(p), "f"(a), "f"(b), "f"(c), "f"(d) : "memory");
}
__device__ __forceinline__ float siluf(float v) {
    return v * (1.0f / (1.0f + __expf(-v)));
}

struct Acc { unsigned long long a[4][4]; };

__device__ __forceinline__ void init_bias(Acc& acc, const float* bias, int tx8) {
    const ulonglong2* b = reinterpret_cast<const ulonglong2*>(bias + tx8);
    ulonglong2 b01 = b[0], b23 = b[1];
#pragma unroll
    for (int i = 0; i < 4; i++) {
        acc.a[i][0] = b01.x; acc.a[i][1] = b01.y;
        acc.a[i][2] = b23.x; acc.a[i][3] = b23.y;
    }
}
__device__ __forceinline__ void init_zero(Acc& acc) {
#pragma unroll
    for (int i = 0; i < 4; i++)
#pragma unroll
        for (int j = 0; j < 4; j++) acc.a[i][j] = 0ull;
}

// A is k-major [KN][tile], swizzled columns, row stride AS; W is [KN][WS] row-major.
template<int KN, int AS, int WS>
__device__ __forceinline__ void gemm_tile(const float* __restrict__ sA,
                                          const float* __restrict__ sW,
                                          int ty4, int tx8, Acc& acc) {
#pragma unroll 8
    for (int k = 0; k < KN; k++) {
        float4 av = *reinterpret_cast<const float4*>(sA + k * AS + swz(k, ty4));
        const ulonglong2* bp = reinterpret_cast<const ulonglong2*>(sW + k * WS + tx8);
        ulonglong2 b01 = bp[0];
        ulonglong2 b23 = bp[1];
        unsigned long long a0 = pk2(av.x, av.x);
        fma2(acc.a[0][0], a0, b01.x); fma2(acc.a[0][1], a0, b01.y);
        fma2(acc.a[0][2], a0, b23.x); fma2(acc.a[0][3], a0, b23.y);
        unsigned long long a1 = pk2(av.y, av.y);
        fma2(acc.a[1][0], a1, b01.x); fma2(acc.a[1][1], a1, b01.y);
        fma2(acc.a[1][2], a1, b23.x); fma2(acc.a[1][3], a1, b23.y);
        unsigned long long a2 = pk2(av.z, av.z);
        fma2(acc.a[2][0], a2, b01.x); fma2(acc.a[2][1], a2, b01.y);
        fma2(acc.a[2][2], a2, b23.x); fma2(acc.a[2][3], a2, b23.y);
        unsigned long long a3 = pk2(av.w, av.w);
        fma2(acc.a[3][0], a3, b01.x); fma2(acc.a[3][1], a3, b01.y);
        fma2(acc.a[3][2], a3, b23.x); fma2(acc.a[3][3], a3, b23.y);
    }
}

__device__ __forceinline__ void unpack_acc(const Acc& acc, float r[4][8]) {
#pragma unroll
    for (int i = 0; i < 4; i++)
#pragma unroll
        for (int j = 0; j < 4; j++) {
            float2 v = up2(acc.a[i][j]);
            r[i][2*j] = v.x; r[i][2*j+1] = v.y;
        }
}
__device__ __forceinline__ void silu_r(float r[4][8]) {
#pragma unroll
    for (int i = 0; i < 4; i++)
#pragma unroll
        for (int c = 0; c < 8; c++) r[i][c] = siluf(r[i][c]);
}
// write activated tile back k-major transposed (swizzled)
template<int AS>
__device__ __forceinline__ void store_t(float* __restrict__ sA, int ty4, int tx8, const float r[4][8]) {
#pragma unroll
    for (int c = 0; c < 8; c++) {
        int row = tx8 + c;
        float4 v = make_float4(r[0][c], r[1][c], r[2][c], r[3][c]);
        *reinterpret_cast<float4*>(sA + row * AS + swz(row, ty4)) = v;
    }
}

// ---------------- zero kernel ----------------
__global__ void zero_kernel(float* __restrict__ hn, float* __restrict__ xs, int nh, int nx) {
    int i = blockIdx.x * blockDim.x + threadIdx.x;
    int st = gridDim.x * blockDim.x;
    for (int j = i; j < nh; j += st) hn[j] = 0.0f;
    for (int j = i; j < nx; j += st) xs[j] = 0.0f;
}

// ---------------- per-node precompute: Ps = h@W1s, Pd = h@W1d + b1 ----------------
#define PRE_SMEM_FLOATS (2*C*C + C + C*SAS)
#define PRE_SMEM_BYTES  (PRE_SMEM_FLOATS * 4)

__global__ void __launch_bounds__(BT, 2) pre_kernel(
    const float* __restrict__ h, const float* __restrict__ w1,
    const float* __restrict__ b1,
    float* __restrict__ Ps, float* __restrict__ Pd, int N)
{
    extern __shared__ float sm[];
    float* sWs = sm;             // rows 0..63 of W1
    float* sWd = sWs + C*C;      // rows 64..127 of W1
    float* sB1 = sWd + C*C;
    float* sA  = sB1 + C;        // 64 x 132 k-major, swizzled

    const int tid = threadIdx.x;
    for (int i = tid; i < C*C; i += BT) { sWs[i] = w1[i]; sWd[i] = w1[C*C + i]; }
    if (tid < C) sB1[tid] = b1[tid];

    const int base = blockIdx.x * TE;
    // stage h tile (k-major, swizzled)
    {
        const int el = tid >> 1, half = tid & 1;
        const int n = base + el;
        const bool v = (n < N);
        const float4 z4 = make_float4(0.f, 0.f, 0.f, 0.f);
#pragma unroll
        for (int i = 0; i < 8; i++) {
            int k = half*32 + i*4;
            float4 vh = v ? *reinterpret_cast<const float4*>(h + (size_t)n*C + k) : z4;
            sA[(k+0)*SAS + swz(k+0, el)] = vh.x;
            sA[(k+1)*SAS + swz(k+1, el)] = vh.y;
            sA[(k+2)*SAS + swz(k+2, el)] = vh.z;
            sA[(k+3)*SAS + swz(k+3, el)] = vh.w;
        }
    }
    __syncthreads();

    const int tx8 = (tid & 7) * 8;
    const int ty4 = (tid >> 3) * 4;

    Acc acc;
    init_zero(acc);
    gemm_tile<C, SAS, C>(sA, sWs, ty4, tx8, acc);
    float r[4][8];
    unpack_acc(acc, r);
#pragma unroll
    for (int i = 0; i < 4; i++) {
        int n = base + ty4 + i;
        if (n < N) {
            float* p = Ps + (size_t)n*C + tx8;
            *reinterpret_cast<float4*>(p)     = make_float4(r[i][0], r[i][1], r[i][2], r[i][3]);
            *reinterpret_cast<float4*>(p + 4) = make_float4(r[i][4], r[i][5], r[i][6], r[i][7]);
        }
    }
    init_bias(acc, sB1, tx8);
    gemm_tile<C, SAS, C>(sA, sWd, ty4, tx8, acc);
    unpack_acc(acc, r);
#pragma unroll
    for (int i = 0; i < 4; i++) {
        int n = base + ty4 + i;
        if (n < N) {
            float* p = Pd + (size_t)n*C + tx8;
            *reinterpret_cast<float4*>(p)     = make_float4(r[i][0], r[i][1], r[i][2], r[i][3]);
            *reinterpret_cast<float4*>(p + 4) = make_float4(r[i][4], r[i][5], r[i][6], r[i][7]);
        }
    }
}

// ---------------- edge kernel ----------------
// smem: W2(64x64) b2 CW1(64x64) cb1 cw2 w1r | A(64x132) | xd(3x128) dst(128)
#define EDGE_SMEM_FLOATS (C*C + C + C*C + C + C + C + C*SAS + 3*TE + TE)
#define EDGE_SMEM_BYTES  (EDGE_SMEM_FLOATS * 4)

__global__ void __launch_bounds__(BT, 2) edge_kernel(
    const float* __restrict__ Ps, const float* __restrict__ Pd,
    const float* __restrict__ w1r,
    const float* __restrict__ x,
    const int* __restrict__ src, const int* __restrict__ dst,
    const float* __restrict__ ew2, const float* __restrict__ eb2,
    const float* __restrict__ cw1, const float* __restrict__ cb1,
    const float* __restrict__ cw2,
    float* __restrict__ hn, float* __restrict__ xs, int E, int do_coord)
{
    extern __shared__ float sm[];
    float* sW2  = sm;
    float* sB2  = sW2 + C*C;
    float* sC1  = sB2 + C;
    float* sCB1 = sC1 + C*C;
    float* sC2  = sCB1 + C;
    float* sW1r = sC2 + C;
    float* sA   = sW1r + C;      // 64 x 132 (k-major, swizzled)
    float* sXd  = sA + C*SAS;    // [3][TE]
    int*   sDst = (int*)(sXd + 3*TE);

    const int tid = threadIdx.x;
    for (int i = tid; i < C*C; i += BT) { sW2[i] = ew2[i]; sC1[i] = cw1[i]; }
    if (tid < C) { sB2[tid] = eb2[tid]; sCB1[tid] = cb1[tid]; sC2[tid] = cw2[tid]; sW1r[tid] = w1r[tid]; }

    const int tx8 = (tid & 7) * 8;
    const int ty4 = (tid >> 3) * 4;
    const int ntiles = (E + TE - 1) / TE;

    for (int tile = blockIdx.x; tile < ntiles; tile += gridDim.x) {
        __syncthreads();
        const int e0 = tile * TE;

        // gather + fused GEMM1 replacement: f1 = silu(Ps[src] + Pd[dst] + radial*w1r)
        {
            const int el = tid >> 1, half = tid & 1;
            const int e = e0 + el;
            const bool v = (e < E);
            const int s = v ? src[e] : 0;
            const int d = v ? dst[e] : 0;
            if (half == 0) sDst[el] = v ? d : -1;
            float dx = x[3*s+0] - x[3*d+0];
            float dy = x[3*s+1] - x[3*d+1];
            float dz = x[3*s+2] - x[3*d+2];
            float rad = dx*dx + dy*dy + dz*dz;     // 0 for invalid (s==d==0)
            if (do_coord && half == 0) {
                float inv = 1.0f / (sqrtf(rad) + 1e-30f);
                sXd[el] = dx*inv; sXd[TE+el] = dy*inv; sXd[2*TE+el] = dz*inv;
            }
            const float* ps = Ps + (size_t)s*C;
            const float* pd = Pd + (size_t)d*C;
            const float4 z4 = make_float4(0.f, 0.f, 0.f, 0.f);
#pragma unroll
            for (int i = 0; i < 8; i++) {
                int k = half*32 + i*4;
                float4 a = v ? *reinterpret_cast<const float4*>(ps + k) : z4;
                float4 b = v ? *reinterpret_cast<const float4*>(pd + k) : z4;
                float4 w = *reinterpret_cast<const float4*>(sW1r + k);
                sA[(k+0)*SAS + swz(k+0, el)] = siluf(a.x + b.x + rad*w.x);
                sA[(k+1)*SAS + swz(k+1, el)] = siluf(a.y + b.y + rad*w.y);
                sA[(k+2)*SAS + swz(k+2, el)] = siluf(a.z + b.z + rad*w.z);
                sA[(k+3)*SAS + swz(k+3, el)] = siluf(a.w + b.w + rad*w.w);
            }
        }
        __syncthreads();

        // GEMM2: msg_h = silu(f1 @ W2 + b2)
        Acc acc;
        init_bias(acc, sB2, tx8);
        gemm_tile<C, SAS, C>(sA, sW2, ty4, tx8, acc);
        float mh[4][8];
        unpack_acc(acc, mh);
        silu_r(mh);

        // scatter msg_h into h_neigh (vector red, no smem involved)
#pragma unroll
        for (int i = 0; i < 4; i++) {
            int d = sDst[ty4 + i];
            if (d >= 0) {
                float* p = hn + (size_t)d*C + tx8;
                redv4(p,     mh[i][0], mh[i][1], mh[i][2], mh[i][3]);
                redv4(p + 4, mh[i][4], mh[i][5], mh[i][6], mh[i][7]);
            }
        }

        if (!do_coord) continue;

        __syncthreads();                 // all readers of sA (f1) done
        store_t<SAS>(sA, ty4, tx8, mh);  // sA <- msg_h (k-major)
        __syncthreads();

        // GEMM3: q = silu(msg_h @ CW1 + cb1); coord_s = q . cw2
        init_bias(acc, sCB1, tx8);
        gemm_tile<C, SAS, C>(sA, sC1, ty4, tx8, acc);
        float q[4][8];
        unpack_acc(acc, q);
        silu_r(q);
        float c2[8];
#pragma unroll
        for (int j = 0; j < 8; j++) c2[j] = sC2[tx8 + j];
        float csum[4];
#pragma unroll
        for (int i = 0; i < 4; i++) {
            float s = 0.f;
#pragma unroll
            for (int j = 0; j < 8; j++) s += q[i][j] * c2[j];
            csum[i] = s;
        }
#pragma unroll
        for (int m = 1; m < 8; m <<= 1) {
#pragma unroll
            for (int i = 0; i < 4; i++)
                csum[i] += __shfl_xor_sync(0xffffffffu, csum[i], m);
        }
        if ((tid & 7) == 0) {
#pragma unroll
            for (int i = 0; i < 4; i++) {
                int el = ty4 + i;
                int d = sDst[el];
                if (d >= 0) {
                    float cs = csum[i];
                    redv4(xs + (size_t)d*4, cs*sXd[el], cs*sXd[TE+el], cs*sXd[2*TE+el], 1.0f);
                }
            }
        }
    }
}

// ---------------- node kernel ----------------
#define NODE_SMEM_FLOATS (2*C*C + C + C*C + C + C + C + 2*C*SAS + C*SAS)
#define NODE_SMEM_BYTES  (NODE_SMEM_FLOATS * 4)

__global__ void __launch_bounds__(BT, 1) node_kernel(
    const float* __restrict__ h, const float* __restrict__ x,
    const float* __restrict__ hn, const float* __restrict__ xs,
    const float* __restrict__ nw1, const float* __restrict__ nb1,
    const float* __restrict__ nw2, const float* __restrict__ nb2,
    const float* __restrict__ lng, const float* __restrict__ lnb,
    float* __restrict__ h_out, float* __restrict__ x_out, int N, int do_x)
{
    extern __shared__ float sm[];
    float* sW1 = sm;              // 128 x 64
    float* sB1 = sW1 + 2*C*C;
    float* sW2 = sB1 + C;
    float* sB2 = sW2 + C*C;
    float* sLG = sB2 + C;
    float* sLB = sLG + C;
    float* sA  = sLB + C;         // 128 x 132 (k-major, swizzled)
    float* sH  = sA + 2*C*SAS;    // 64 x 132

    const int tid = threadIdx.x;
    for (int i = tid; i < 2*C*C; i += BT) sW1[i] = nw1[i];
    for (int i = tid; i < C*C; i += BT) sW2[i] = nw2[i];
    if (tid < C) { sB1[tid] = nb1[tid]; sB2[tid] = nb2[tid]; sLG[tid] = lng[tid]; sLB[tid] = lnb[tid]; }

    const int tx8 = (tid & 7) * 8;
    const int ty4 = (tid >> 3) * 4;
    const int base = blockIdx.x * TE;

    if (do_x && tid < TE) {
        int n = base + tid;
        if (n < N) {
            float4 s = *reinterpret_cast<const float4*>(xs + (size_t)n*4);
            float deg = fmaxf(s.w, 1.0f);
            x_out[3*n+0] = x[3*n+0] + s.x / deg;
            x_out[3*n+1] = x[3*n+1] + s.y / deg;
            x_out[3*n+2] = x[3*n+2] + s.z / deg;
        }
    }

    {
        const int el = tid >> 1, half = tid & 1;
        const int n = base + el;
        const bool v = (n < N);
        const float4 z4 = make_float4(0.f, 0.f, 0.f, 0.f);
#pragma unroll
        for (int i = 0; i < 8; i++) {
            int k = half*32 + i*4;
            float4 vh = v ? *reinterpret_cast<const float4*>(h  + (size_t)n*C + k) : z4;
            float4 vn = v ? *reinterpret_cast<const float4*>(hn + (size_t)n*C + k) : z4;
            sA[(k+0)*SAS + swz(k+0, el)] = vh.x;
            sA[(k+1)*SAS + swz(k+1, el)] = vh.y;
            sA[(k+2)*SAS + swz(k+2, el)] = vh.z;
            sA[(k+3)*SAS + swz(k+3, el)] = vh.w;
            sA[(C+k+0)*SAS + swz(C+k+0, el)] = vn.x;
            sA[(C+k+1)*SAS + swz(C+k+1, el)] = vn.y;
            sA[(C+k+2)*SAS + swz(C+k+2, el)] = vn.z;
            sA[(C+k+3)*SAS + swz(C+k+3, el)] = vn.w;
        }
    }
    __syncthreads();

    Acc acc;
    init_bias(acc, sB1, tx8);
    gemm_tile<2*C, SAS, C>(sA, sW1, ty4, tx8, acc);
    __syncthreads();
    float r1[4][8];
    unpack_acc(acc, r1);
    silu_r(r1);
    store_t<SAS>(sH, ty4, tx8, r1);
    __syncthreads();

    init_bias(acc, sB2, tx8);
    gemm_tile<C, SAS, C>(sH, sW2, ty4, tx8, acc);
    float r2[4][8];
    unpack_acc(acc, r2);

#pragma unroll
    for (int i = 0; i < 4; i++) {
        float s1 = 0.f, s2 = 0.f;
#pragma unroll
        for (int c = 0; c < 8; c++) {
            float v = r2[i][c];
            v = 0.5f * v * (1.0f + erff(v * 0.70710678118654752f));
            r2[i][c] = v;
            s1 += v; s2 += v*v;
        }
#pragma unroll
        for (int m = 1; m < 8; m <<= 1) {
            s1 += __shfl_xor_sync(0xffffffffu, s1, m);
            s2 += __shfl_xor_sync(0xffffffffu, s2, m);
        }
        float mu = s1 * (1.0f / C);
        float var = s2 * (1.0f / C) - mu * mu;
        float inv = rsqrtf(var + 1e-5f);
        int n = base + ty4 + i;
        if (n < N) {
            float o[8];
#pragma unroll
            for (int c = 0; c < 8; c++)
                o[c] = (r2[i][c] - mu) * inv * sLG[tx8 + c] + sLB[tx8 + c];
            float* p = h_out + (size_t)n*C + tx8;
            *reinterpret_cast<float4*>(p)     = make_float4(o[0], o[1], o[2], o[3]);
            *reinterpret_cast<float4*>(p + 4) = make_float4(o[4], o[5], o[6], o[7]);
        }
    }
}

// ---------------- output head ----------------
#define OTILE 256
#define OAS 260
#define OUT_SMEM_FLOATS (C*OAS + C*NOUTC + NOUTC)
#define OUT_SMEM_BYTES  (OUT_SMEM_FLOATS * 4)

__global__ void __launch_bounds__(BT, 2) out_kernel(
    const float* __restrict__ h, const float* __restrict__ ow,
    const float* __restrict__ ob, float* __restrict__ out, int N)
{
    extern __shared__ float sm[];
    float* sA = sm;              // 64 x 260 (k-major, swizzled)
    float* sW = sA + C*OAS;
    float* sB = sW + C*NOUTC;

    const int tid = threadIdx.x;
    for (int i = tid; i < C*NOUTC; i += BT) sW[i] = ow[i];
    if (tid < NOUTC) sB[tid] = ob[tid];

    const int base = blockIdx.x * OTILE;
    {
        const float4* hg = reinterpret_cast<const float4*>(h + (size_t)base * C);
        const float4 z4 = make_float4(0.f, 0.f, 0.f, 0.f);
        for (int idx = tid; idx < OTILE * (C/4); idx += BT) {
            int p = idx * 4;
            int ln = p >> 6;
            int k = p & 63;
            float4 v = (base + ln < N) ? hg[idx] : z4;
            sA[(k+0)*OAS + swz(k+0, ln)] = v.x;
            sA[(k+1)*OAS + swz(k+1, ln)] = v.y;
            sA[(k+2)*OAS + swz(k+2, ln)] = v.z;
            sA[(k+3)*OAS + swz(k+3, ln)] = v.w;
        }
    }
    __syncthreads();

    const int tx8 = (tid & 3) * 8;
    const int ty4 = (tid >> 2) * 4;
    Acc acc;
    init_bias(acc, sB, tx8);
    gemm_tile<C, OAS, NOUTC>(sA, sW, ty4, tx8, acc);
    float r[4][8];
    unpack_acc(acc, r);
#pragma unroll
    for (int i = 0; i < 4; i++) {
        int n = base + ty4 + i;
        if (n < N) {
            float* p = out + (size_t)n * NOUTC + tx8;
            *reinterpret_cast<float4*>(p)     = make_float4(r[i][0], r[i][1], r[i][2], r[i][3]);
            *reinterpret_cast<float4*>(p + 4) = make_float4(r[i][4], r[i][5], r[i][6], r[i][7]);
        }
    }
}

// ---------------- launch ----------------
extern "C" void kernel_launch(void* const* d_in, const int* in_sizes, int n_in,
                              void* d_out, int out_size) {
    const float* node_feat = (const float*)d_in[0];
    const float* xyz = (const float*)d_in[1];
    const int* src = (const int*)d_in[2];
    const int* dst = (const int*)d_in[3];
    const float* ew1 = (const float*)d_in[4];
    const float* eb1 = (const float*)d_in[5];
    const float* ew2 = (const float*)d_in[6];
    const float* eb2 = (const float*)d_in[7];
    const float* cw1 = (const float*)d_in[8];
    const float* cb1 = (const float*)d_in[9];
    const float* cw2 = (const float*)d_in[10];
    const float* nw1 = (const float*)d_in[11];
    const float* nb1 = (const float*)d_in[12];
    const float* nw2 = (const float*)d_in[13];
    const float* nb2 = (const float*)d_in[14];
    const float* lng = (const float*)d_in[15];
    const float* lnb = (const float*)d_in[16];
    const float* ow  = (const float*)d_in[17];
    const float* ob  = (const float*)d_in[18];

    const int N = in_sizes[0] / C;
    const int E = in_sizes[2];

    float *hA, *hB, *xA, *hn, *xs, *Ps, *Pd;
    cudaGetSymbolAddress((void**)&hA, g_hA);
    cudaGetSymbolAddress((void**)&hB, g_hB);
    cudaGetSymbolAddress((void**)&xA, g_xA);
    cudaGetSymbolAddress((void**)&hn, g_hn);
    cudaGetSymbolAddress((void**)&xs, g_xs);
    cudaGetSymbolAddress((void**)&Ps, g_Ps);
    cudaGetSymbolAddress((void**)&Pd, g_Pd);

    cudaFuncSetAttribute(pre_kernel,  cudaFuncAttributeMaxDynamicSharedMemorySize, PRE_SMEM_BYTES);
    cudaFuncSetAttribute(edge_kernel, cudaFuncAttributeMaxDynamicSharedMemorySize, EDGE_SMEM_BYTES);
    cudaFuncSetAttribute(node_kernel, cudaFuncAttributeMaxDynamicSharedMemorySize, NODE_SMEM_BYTES);
    cudaFuncSetAttribute(out_kernel,  cudaFuncAttributeMaxDynamicSharedMemorySize, OUT_SMEM_BYTES);

    const int ntiles_n = (N + TE - 1) / TE;
    const int ntiles_o = (N + OTILE - 1) / OTILE;

    // layer 0
    pre_kernel<<<ntiles_n, BT, PRE_SMEM_BYTES>>>(node_feat, ew1, eb1, Ps, Pd, N);
    zero_kernel<<<512, BT>>>(hn, xs, N*C, N*4);
    edge_kernel<<<296, BT, EDGE_SMEM_BYTES>>>(Ps, Pd, ew1 + 128*C, xyz, src, dst,
        ew2, eb2, cw1, cb1, cw2, hn, xs, E, 1);
    node_kernel<<<ntiles_n, BT, NODE_SMEM_BYTES>>>(node_feat, xyz, hn, xs,
        nw1, nb1, nw2, nb2, lng, lnb, hA, xA, N, 1);

    // layer 1 (coord path + x update dead w.r.t. output -> skipped)
    pre_kernel<<<ntiles_n, BT, PRE_SMEM_BYTES>>>(hA, ew1 + 129*C, eb1 + C, Ps, Pd, N);
    zero_kernel<<<512, BT>>>(hn, xs, N*C, 0);
    edge_kernel<<<296, BT, EDGE_SMEM_BYTES>>>(Ps, Pd, ew1 + 129*C + 128*C, xA, src, dst,
        ew2 + C*C, eb2 + C, cw1 + C*C, cb1 + C, cw2 + C, hn, xs, E, 0);
    node_kernel<<<ntiles_n, BT, NODE_SMEM_BYTES>>>(hA, xA, hn, xs,
        nw1 + 2*C*C, nb1 + C, nw2 + C*C, nb2 + C, lng, lnb, hB, xA, N, 0);

    out_kernel<<<ntiles_o, BT, OUT_SMEM_BYTES>>>(hB, ow, ob, (float*)d_out, N);
}

// round 8
// speedup vs baseline: 2.3789x; 1.0434x over previous
#include <cuda_runtime.h>
#include <math.h>

#define C 64
#define TE 128
#define BT 256
#define SAS 132
#define NOUTC 32
#define NMAX 100000
#define EMAX 1600000
#define SCB 1024

// ---------------- scratch (device globals; no allocation) ----------------
__device__ float g_hA[(size_t)NMAX * C];
__device__ float g_hB[(size_t)NMAX * C];
__device__ float g_xA[(size_t)NMAX * 3];
__device__ float g_hn[(size_t)NMAX * C];
__device__ float g_xs[(size_t)NMAX * 4];
__device__ float g_Ps[(size_t)NMAX * C];
__device__ float g_Pd[(size_t)NMAX * C];
__device__ int   g_cnt[NMAX];
__device__ int   g_cur[NMAX];
__device__ int   g_off[NMAX];
__device__ int   g_bsum[128];
__device__ int   g_perm[EMAX];

// ---------------- helpers ----------------
__device__ __forceinline__ int swz(int row, int col) {
    return col ^ (((row >> 3) & 7) << 2);
}
__device__ __forceinline__ unsigned long long pk2(float x, float y) {
    unsigned long long r;
    asm("mov.b64 %0, {%1, %2};" : "=l"(r) : "f"(x), "f"(y));
    return r;
}
__device__ __forceinline__ float2 up2(unsigned long long v) {
    float lo, hi;
    asm("mov.b64 {%0, %1}, %2;" : "=f"(lo), "=f"(hi) : "l"(v));
    return make_float2(lo, hi);
}
__device__ __forceinline__ void fma2(unsigned long long& d, unsigned long long a, unsigned long long b) {
    asm("fma.rn.f32x2 %0, %1, %2, %0;" : "+l"(d) : "l"(a), "l"(b));
}
__device__ __forceinline__ void redv4(float* p, float a, float b, float c, float d) {
    asm volatile("red.global.add.v4.f32 [%0], {%1, %2, %3, %4};"
                 :: "l"(p), "f"(a), "f"(b), "f"(c), "f"(d) : "memory");
}
__device__ __forceinline__ float siluf(float v) {
    return v * (1.0f / (1.0f + __expf(-v)));
}

struct Acc { unsigned long long a[4][4]; };

__device__ __forceinline__ void init_bias(Acc& acc, const float* bias, int tx8) {
    const ulonglong2* b = reinterpret_cast<const ulonglong2*>(bias + tx8);
    ulonglong2 b01 = b[0], b23 = b[1];
#pragma unroll
    for (int i = 0; i < 4; i++) {
        acc.a[i][0] = b01.x; acc.a[i][1] = b01.y;
        acc.a[i][2] = b23.x; acc.a[i][3] = b23.y;
    }
}
__device__ __forceinline__ void init_zero(Acc& acc) {
#pragma unroll
    for (int i = 0; i < 4; i++)
#pragma unroll
        for (int j = 0; j < 4; j++) acc.a[i][j] = 0ull;
}

// A is k-major [KN][tile], swizzled columns, row stride AS; W is [KN][WS] row-major.
template<int KN, int AS, int WS>
__device__ __forceinline__ void gemm_tile(const float* __restrict__ sA,
                                          const float* __restrict__ sW,
                                          int ty4, int tx8, Acc& acc) {
#pragma unroll 8
    for (int k = 0; k < KN; k++) {
        float4 av = *reinterpret_cast<const float4*>(sA + k * AS + swz(k, ty4));
        const ulonglong2* bp = reinterpret_cast<const ulonglong2*>(sW + k * WS + tx8);
        ulonglong2 b01 = bp[0];
        ulonglong2 b23 = bp[1];
        unsigned long long a0 = pk2(av.x, av.x);
        fma2(acc.a[0][0], a0, b01.x); fma2(acc.a[0][1], a0, b01.y);
        fma2(acc.a[0][2], a0, b23.x); fma2(acc.a[0][3], a0, b23.y);
        unsigned long long a1 = pk2(av.y, av.y);
        fma2(acc.a[1][0], a1, b01.x); fma2(acc.a[1][1], a1, b01.y);
        fma2(acc.a[1][2], a1, b23.x); fma2(acc.a[1][3], a1, b23.y);
        unsigned long long a2 = pk2(av.z, av.z);
        fma2(acc.a[2][0], a2, b01.x); fma2(acc.a[2][1], a2, b01.y);
        fma2(acc.a[2][2], a2, b23.x); fma2(acc.a[2][3], a2, b23.y);
        unsigned long long a3 = pk2(av.w, av.w);
        fma2(acc.a[3][0], a3, b01.x); fma2(acc.a[3][1], a3, b01.y);
        fma2(acc.a[3][2], a3, b23.x); fma2(acc.a[3][3], a3, b23.y);
    }
}

__device__ __forceinline__ void unpack_acc(const Acc& acc, float r[4][8]) {
#pragma unroll
    for (int i = 0; i < 4; i++)
#pragma unroll
        for (int j = 0; j < 4; j++) {
            float2 v = up2(acc.a[i][j]);
            r[i][2*j] = v.x; r[i][2*j+1] = v.y;
        }
}
__device__ __forceinline__ void silu_r(float r[4][8]) {
#pragma unroll
    for (int i = 0; i < 4; i++)
#pragma unroll
        for (int c = 0; c < 8; c++) r[i][c] = siluf(r[i][c]);
}
template<int AS>
__device__ __forceinline__ void store_t(float* __restrict__ sA, int ty4, int tx8, const float r[4][8]) {
#pragma unroll
    for (int c = 0; c < 8; c++) {
        int row = tx8 + c;
        float4 v = make_float4(r[0][c], r[1][c], r[2][c], r[3][c]);
        *reinterpret_cast<float4*>(sA + row * AS + swz(row, ty4)) = v;
    }
}

// ---------------- sort-by-dst (counting sort) ----------------
__global__ void zero_int_kernel(int* __restrict__ cnt, int* __restrict__ cur, int N) {
    int i = blockIdx.x * blockDim.x + threadIdx.x;
    if (i < N) { cnt[i] = 0; cur[i] = 0; }
}
__global__ void hist_kernel(const int* __restrict__ dst, int* __restrict__ cnt, int E) {
    int e = blockIdx.x * blockDim.x + threadIdx.x;
    if (e < E) atomicAdd(&cnt[dst[e]], 1);
}
__global__ void scan1_kernel(const int* __restrict__ cnt, int* __restrict__ off,
                             int* __restrict__ bsum, int N) {
    __shared__ int sm[256];
    const int t = threadIdx.x;
    const int base = blockIdx.x * SCB + t * 4;
    int c0 = (base+0 < N) ? cnt[base+0] : 0;
    int c1 = (base+1 < N) ? cnt[base+1] : 0;
    int c2 = (base+2 < N) ? cnt[base+2] : 0;
    int c3 = (base+3 < N) ? cnt[base+3] : 0;
    int tot = c0 + c1 + c2 + c3;
    sm[t] = tot;
    __syncthreads();
#pragma unroll
    for (int d = 1; d < 256; d <<= 1) {
        int v = (t >= d) ? sm[t - d] : 0;
        __syncthreads();
        sm[t] += v;
        __syncthreads();
    }
    int ex = sm[t] - tot;   // exclusive within block
    if (t == 255) bsum[blockIdx.x] = sm[255];
    if (base+0 < N) off[base+0] = ex;
    if (base+1 < N) off[base+1] = ex + c0;
    if (base+2 < N) off[base+2] = ex + c0 + c1;
    if (base+3 < N) off[base+3] = ex + c0 + c1 + c2;
}
__global__ void scan2_kernel(int* __restrict__ bsum, int nb) {
    __shared__ int sm[128];
    int t = threadIdx.x;
    int v = (t < nb) ? bsum[t] : 0;
    sm[t] = v;
    __syncthreads();
#pragma unroll
    for (int d = 1; d < 128; d <<= 1) {
        int u = (t >= d) ? sm[t - d] : 0;
        __syncthreads();
        sm[t] += u;
        __syncthreads();
    }
    if (t < nb) bsum[t] = sm[t] - v;   // exclusive
}
__global__ void scatter_kernel(const int* __restrict__ dst, const int* __restrict__ off,
                               const int* __restrict__ bsum, int* __restrict__ cur,
                               int* __restrict__ perm, int E) {
    int e = blockIdx.x * blockDim.x + threadIdx.x;
    if (e < E) {
        int d = dst[e];
        int p = off[d] + bsum[d >> 10] + atomicAdd(&cur[d], 1);
        perm[p] = e;
    }
}

// ---------------- zero kernel ----------------
__global__ void zero_kernel(float* __restrict__ hn, float* __restrict__ xs, int nh, int nx) {
    int i = blockIdx.x * blockDim.x + threadIdx.x;
    int st = gridDim.x * blockDim.x;
    for (int j = i; j < nh; j += st) hn[j] = 0.0f;
    for (int j = i; j < nx; j += st) xs[j] = 0.0f;
}

// ---------------- per-node precompute: Ps = h@W1s, Pd = h@W1d + b1 ----------------
#define PRE_SMEM_FLOATS (2*C*C + C + C*SAS)
#define PRE_SMEM_BYTES  (PRE_SMEM_FLOATS * 4)

__global__ void __launch_bounds__(BT, 2) pre_kernel(
    const float* __restrict__ h, const float* __restrict__ w1,
    const float* __restrict__ b1,
    float* __restrict__ Ps, float* __restrict__ Pd, int N)
{
    extern __shared__ float sm[];
    float* sWs = sm;
    float* sWd = sWs + C*C;
    float* sB1 = sWd + C*C;
    float* sA  = sB1 + C;

    const int tid = threadIdx.x;
    for (int i = tid; i < C*C; i += BT) { sWs[i] = w1[i]; sWd[i] = w1[C*C + i]; }
    if (tid < C) sB1[tid] = b1[tid];

    const int base = blockIdx.x * TE;
    {
        const int el = tid >> 1, half = tid & 1;
        const int n = base + el;
        const bool v = (n < N);
        const float4 z4 = make_float4(0.f, 0.f, 0.f, 0.f);
#pragma unroll
        for (int i = 0; i < 8; i++) {
            int k = half*32 + i*4;
            float4 vh = v ? *reinterpret_cast<const float4*>(h + (size_t)n*C + k) : z4;
            sA[(k+0)*SAS + swz(k+0, el)] = vh.x;
            sA[(k+1)*SAS + swz(k+1, el)] = vh.y;
            sA[(k+2)*SAS + swz(k+2, el)] = vh.z;
            sA[(k+3)*SAS + swz(k+3, el)] = vh.w;
        }
    }
    __syncthreads();

    const int tx8 = (tid & 7) * 8;
    const int ty4 = (tid >> 3) * 4;

    Acc acc;
    init_zero(acc);
    gemm_tile<C, SAS, C>(sA, sWs, ty4, tx8, acc);
    float r[4][8];
    unpack_acc(acc, r);
#pragma unroll
    for (int i = 0; i < 4; i++) {
        int n = base + ty4 + i;
        if (n < N) {
            float* p = Ps + (size_t)n*C + tx8;
            *reinterpret_cast<float4*>(p)     = make_float4(r[i][0], r[i][1], r[i][2], r[i][3]);
            *reinterpret_cast<float4*>(p + 4) = make_float4(r[i][4], r[i][5], r[i][6], r[i][7]);
        }
    }
    init_bias(acc, sB1, tx8);
    gemm_tile<C, SAS, C>(sA, sWd, ty4, tx8, acc);
    unpack_acc(acc, r);
#pragma unroll
    for (int i = 0; i < 4; i++) {
        int n = base + ty4 + i;
        if (n < N) {
            float* p = Pd + (size_t)n*C + tx8;
            *reinterpret_cast<float4*>(p)     = make_float4(r[i][0], r[i][1], r[i][2], r[i][3]);
            *reinterpret_cast<float4*>(p + 4) = make_float4(r[i][4], r[i][5], r[i][6], r[i][7]);
        }
    }
}

// ---------------- edge kernel (edges permuted: sorted by dst) ----------------
#define EDGE_SMEM_FLOATS (C*C + C + C*C + C + C + C + C*SAS + 3*TE + TE)
#define EDGE_SMEM_BYTES  (EDGE_SMEM_FLOATS * 4)

__global__ void __launch_bounds__(BT, 2) edge_kernel(
    const float* __restrict__ Ps, const float* __restrict__ Pd,
    const float* __restrict__ w1r,
    const float* __restrict__ x,
    const int* __restrict__ src, const int* __restrict__ dst,
    const int* __restrict__ perm,
    const float* __restrict__ ew2, const float* __restrict__ eb2,
    const float* __restrict__ cw1, const float* __restrict__ cb1,
    const float* __restrict__ cw2,
    float* __restrict__ hn, float* __restrict__ xs, int E, int do_coord)
{
    extern __shared__ float sm[];
    float* sW2  = sm;
    float* sB2  = sW2 + C*C;
    float* sC1  = sB2 + C;
    float* sCB1 = sC1 + C*C;
    float* sC2  = sCB1 + C;
    float* sW1r = sC2 + C;
    float* sA   = sW1r + C;      // 64 x 132 (k-major, swizzled)
    float* sXd  = sA + C*SAS;    // [3][TE]
    int*   sDst = (int*)(sXd + 3*TE);

    const int tid = threadIdx.x;
    for (int i = tid; i < C*C; i += BT) { sW2[i] = ew2[i]; sC1[i] = cw1[i]; }
    if (tid < C) { sB2[tid] = eb2[tid]; sCB1[tid] = cb1[tid]; sC2[tid] = cw2[tid]; sW1r[tid] = w1r[tid]; }

    const int tx8 = (tid & 7) * 8;
    const int ty4 = (tid >> 3) * 4;
    const int ntiles = (E + TE - 1) / TE;

    for (int tile = blockIdx.x; tile < ntiles; tile += gridDim.x) {
        __syncthreads();
        const int e0 = tile * TE;

        // gather + fused GEMM1 replacement: f1 = silu(Ps[src] + Pd[dst] + radial*w1r)
        {
            const int el = tid >> 1, half = tid & 1;
            const bool v = (e0 + el < E);
            const int e = v ? perm[e0 + el] : 0;
            const int s = v ? src[e] : 0;
            const int d = v ? dst[e] : 0;
            if (half == 0) sDst[el] = v ? d : -1;
            float dx = x[3*s+0] - x[3*d+0];
            float dy = x[3*s+1] - x[3*d+1];
            float dz = x[3*s+2] - x[3*d+2];
            float rad = dx*dx + dy*dy + dz*dz;
            if (do_coord && half == 0) {
                float inv = 1.0f / (sqrtf(rad) + 1e-30f);
                sXd[el] = dx*inv; sXd[TE+el] = dy*inv; sXd[2*TE+el] = dz*inv;
            }
            const float* ps = Ps + (size_t)s*C;
            const float* pd = Pd + (size_t)d*C;
            const float4 z4 = make_float4(0.f, 0.f, 0.f, 0.f);
#pragma unroll
            for (int i = 0; i < 8; i++) {
                int k = half*32 + i*4;
                float4 a = v ? *reinterpret_cast<const float4*>(ps + k) : z4;
                float4 b = v ? *reinterpret_cast<const float4*>(pd + k) : z4;
                float4 w = *reinterpret_cast<const float4*>(sW1r + k);
                sA[(k+0)*SAS + swz(k+0, el)] = siluf(a.x + b.x + rad*w.x);
                sA[(k+1)*SAS + swz(k+1, el)] = siluf(a.y + b.y + rad*w.y);
                sA[(k+2)*SAS + swz(k+2, el)] = siluf(a.z + b.z + rad*w.z);
                sA[(k+3)*SAS + swz(k+3, el)] = siluf(a.w + b.w + rad*w.w);
            }
        }
        __syncthreads();

        // GEMM2: msg_h = silu(f1 @ W2 + b2)
        Acc acc;
        init_bias(acc, sB2, tx8);
        gemm_tile<C, SAS, C>(sA, sW2, ty4, tx8, acc);
        float mh[4][8];
        unpack_acc(acc, mh);
        silu_r(mh);

        // quad-merged scatter (dst sorted -> consecutive edges often share dst)
        {
            int d0 = sDst[ty4+0], d1 = sDst[ty4+1], d2 = sDst[ty4+2], d3 = sDst[ty4+3];
            float v[8];
#pragma unroll
            for (int c = 0; c < 8; c++) v[c] = mh[0][c];
            int dcur = d0;
#pragma unroll
            for (int i = 1; i < 4; i++) {
                int d = (i == 1) ? d1 : (i == 2) ? d2 : d3;
                if (d == dcur) {
#pragma unroll
                    for (int c = 0; c < 8; c++) v[c] += mh[i][c];
                } else {
                    if (dcur >= 0) {
                        float* p = hn + (size_t)dcur*C + tx8;
                        redv4(p,     v[0], v[1], v[2], v[3]);
                        redv4(p + 4, v[4], v[5], v[6], v[7]);
                    }
                    dcur = d;
#pragma unroll
                    for (int c = 0; c < 8; c++) v[c] = mh[i][c];
                }
            }
            if (dcur >= 0) {
                float* p = hn + (size_t)dcur*C + tx8;
                redv4(p,     v[0], v[1], v[2], v[3]);
                redv4(p + 4, v[4], v[5], v[6], v[7]);
            }
        }

        if (!do_coord) continue;

        __syncthreads();
        store_t<SAS>(sA, ty4, tx8, mh);
        __syncthreads();

        // GEMM3: q = silu(msg_h @ CW1 + cb1); coord_s = q . cw2
        init_bias(acc, sCB1, tx8);
        gemm_tile<C, SAS, C>(sA, sC1, ty4, tx8, acc);
        float q[4][8];
        unpack_acc(acc, q);
        silu_r(q);
        float c2[8];
#pragma unroll
        for (int j = 0; j < 8; j++) c2[j] = sC2[tx8 + j];
        float csum[4];
#pragma unroll
        for (int i = 0; i < 4; i++) {
            float s = 0.f;
#pragma unroll
            for (int j = 0; j < 8; j++) s += q[i][j] * c2[j];
            csum[i] = s;
        }
#pragma unroll
        for (int m = 1; m < 8; m <<= 1) {
#pragma unroll
            for (int i = 0; i < 4; i++)
                csum[i] += __shfl_xor_sync(0xffffffffu, csum[i], m);
        }
        if ((tid & 7) == 0) {
            // merged coord scatter over the 4 sorted edges
            int d0 = sDst[ty4+0], d1 = sDst[ty4+1], d2 = sDst[ty4+2], d3 = sDst[ty4+3];
            float vx = csum[0]*sXd[ty4+0], vy = csum[0]*sXd[TE+ty4+0], vz = csum[0]*sXd[2*TE+ty4+0];
            int dcur = d0;
#pragma unroll
            for (int i = 1; i < 4; i++) {
                int el = ty4 + i;
                int d = (i == 1) ? d1 : (i == 2) ? d2 : d3;
                float ax = csum[i]*sXd[el], ay = csum[i]*sXd[TE+el], az = csum[i]*sXd[2*TE+el];
                if (d == dcur) { vx += ax; vy += ay; vz += az; }
                else {
                    if (dcur >= 0) redv4(xs + (size_t)dcur*4, vx, vy, vz, 0.0f);
                    dcur = d; vx = ax; vy = ay; vz = az;
                }
            }
            if (dcur >= 0) redv4(xs + (size_t)dcur*4, vx, vy, vz, 0.0f);
        }
    }
}

// ---------------- node kernel ----------------
#define NODE_SMEM_FLOATS (2*C*C + C + C*C + C + C + C + 2*C*SAS + C*SAS)
#define NODE_SMEM_BYTES  (NODE_SMEM_FLOATS * 4)

__global__ void __launch_bounds__(BT, 1) node_kernel(
    const float* __restrict__ h, const float* __restrict__ x,
    const float* __restrict__ hn, const float* __restrict__ xs,
    const int* __restrict__ cnt,
    const float* __restrict__ nw1, const float* __restrict__ nb1,
    const float* __restrict__ nw2, const float* __restrict__ nb2,
    const float* __restrict__ lng, const float* __restrict__ lnb,
    float* __restrict__ h_out, float* __restrict__ x_out, int N, int do_x)
{
    extern __shared__ float sm[];
    float* sW1 = sm;
    float* sB1 = sW1 + 2*C*C;
    float* sW2 = sB1 + C;
    float* sB2 = sW2 + C*C;
    float* sLG = sB2 + C;
    float* sLB = sLG + C;
    float* sA  = sLB + C;
    float* sH  = sA + 2*C*SAS;

    const int tid = threadIdx.x;
    for (int i = tid; i < 2*C*C; i += BT) sW1[i] = nw1[i];
    for (int i = tid; i < C*C; i += BT) sW2[i] = nw2[i];
    if (tid < C) { sB1[tid] = nb1[tid]; sB2[tid] = nb2[tid]; sLG[tid] = lng[tid]; sLB[tid] = lnb[tid]; }

    const int tx8 = (tid & 7) * 8;
    const int ty4 = (tid >> 3) * 4;
    const int base = blockIdx.x * TE;

    if (do_x && tid < TE) {
        int n = base + tid;
        if (n < N) {
            float4 s = *reinterpret_cast<const float4*>(xs + (size_t)n*4);
            float deg = fmaxf((float)cnt[n], 1.0f);
            x_out[3*n+0] = x[3*n+0] + s.x / deg;
            x_out[3*n+1] = x[3*n+1] + s.y / deg;
            x_out[3*n+2] = x[3*n+2] + s.z / deg;
        }
    }

    {
        const int el = tid >> 1, half = tid & 1;
        const int n = base + el;
        const bool v = (n < N);
        const float4 z4 = make_float4(0.f, 0.f, 0.f, 0.f);
#pragma unroll
        for (int i = 0; i < 8; i++) {
            int k = half*32 + i*4;
            float4 vh = v ? *reinterpret_cast<const float4*>(h  + (size_t)n*C + k) : z4;
            float4 vn = v ? *reinterpret_cast<const float4*>(hn + (size_t)n*C + k) : z4;
            sA[(k+0)*SAS + swz(k+0, el)] = vh.x;
            sA[(k+1)*SAS + swz(k+1, el)] = vh.y;
            sA[(k+2)*SAS + swz(k+2, el)] = vh.z;
            sA[(k+3)*SAS + swz(k+3, el)] = vh.w;
            sA[(C+k+0)*SAS + swz(C+k+0, el)] = vn.x;
            sA[(C+k+1)*SAS + swz(C+k+1, el)] = vn.y;
            sA[(C+k+2)*SAS + swz(C+k+2, el)] = vn.z;
            sA[(C+k+3)*SAS + swz(C+k+3, el)] = vn.w;
        }
    }
    __syncthreads();

    Acc acc;
    init_bias(acc, sB1, tx8);
    gemm_tile<2*C, SAS, C>(sA, sW1, ty4, tx8, acc);
    __syncthreads();
    float r1[4][8];
    unpack_acc(acc, r1);
    silu_r(r1);
    store_t<SAS>(sH, ty4, tx8, r1);
    __syncthreads();

    init_bias(acc, sB2, tx8);
    gemm_tile<C, SAS, C>(sH, sW2, ty4, tx8, acc);
    float r2[4][8];
    unpack_acc(acc, r2);

#pragma unroll
    for (int i = 0; i < 4; i++) {
        float s1 = 0.f, s2 = 0.f;
#pragma unroll
        for (int c = 0; c < 8; c++) {
            float v = r2[i][c];
            v = 0.5f * v * (1.0f + erff(v * 0.70710678118654752f));
            r2[i][c] = v;
            s1 += v; s2 += v*v;
        }
#pragma unroll
        for (int m = 1; m < 8; m <<= 1) {
            s1 += __shfl_xor_sync(0xffffffffu, s1, m);
            s2 += __shfl_xor_sync(0xffffffffu, s2, m);
        }
        float mu = s1 * (1.0f / C);
        float var = s2 * (1.0f / C) - mu * mu;
        float inv = rsqrtf(var + 1e-5f);
        int n = base + ty4 + i;
        if (n < N) {
            float o[8];
#pragma unroll
            for (int c = 0; c < 8; c++)
                o[c] = (r2[i][c] - mu) * inv * sLG[tx8 + c] + sLB[tx8 + c];
            float* p = h_out + (size_t)n*C + tx8;
            *reinterpret_cast<float4*>(p)     = make_float4(o[0], o[1], o[2], o[3]);
            *reinterpret_cast<float4*>(p + 4) = make_float4(o[4], o[5], o[6], o[7]);
        }
    }
}

// ---------------- output head ----------------
#define OTILE 256
#define OAS 260
#define OUT_SMEM_FLOATS (C*OAS + C*NOUTC + NOUTC)
#define OUT_SMEM_BYTES  (OUT_SMEM_FLOATS * 4)

__global__ void __launch_bounds__(BT, 2) out_kernel(
    const float* __restrict__ h, const float* __restrict__ ow,
    const float* __restrict__ ob, float* __restrict__ out, int N)
{
    extern __shared__ float sm[];
    float* sA = sm;
    float* sW = sA + C*OAS;
    float* sB = sW + C*NOUTC;

    const int tid = threadIdx.x;
    for (int i = tid; i < C*NOUTC; i += BT) sW[i] = ow[i];
    if (tid < NOUTC) sB[tid] = ob[tid];

    const int base = blockIdx.x * OTILE;
    {
        const float4* hg = reinterpret_cast<const float4*>(h + (size_t)base * C);
        const float4 z4 = make_float4(0.f, 0.f, 0.f, 0.f);
        for (int idx = tid; idx < OTILE * (C/4); idx += BT) {
            int p = idx * 4;
            int ln = p >> 6;
            int k = p & 63;
            float4 v = (base + ln < N) ? hg[idx] : z4;
            sA[(k+0)*OAS + swz(k+0, ln)] = v.x;
            sA[(k+1)*OAS + swz(k+1, ln)] = v.y;
            sA[(k+2)*OAS + swz(k+2, ln)] = v.z;
            sA[(k+3)*OAS + swz(k+3, ln)] = v.w;
        }
    }
    __syncthreads();

    const int tx8 = (tid & 3) * 8;
    const int ty4 = (tid >> 2) * 4;
    Acc acc;
    init_bias(acc, sB, tx8);
    gemm_tile<C, OAS, NOUTC>(sA, sW, ty4, tx8, acc);
    float r[4][8];
    unpack_acc(acc, r);
#pragma unroll
    for (int i = 0; i < 4; i++) {
        int n = base + ty4 + i;
        if (n < N) {
            float* p = out + (size_t)n * NOUTC + tx8;
            *reinterpret_cast<float4*>(p)     = make_float4(r[i][0], r[i][1], r[i][2], r[i][3]);
            *reinterpret_cast<float4*>(p + 4) = make_float4(r[i][4], r[i][5], r[i][6], r[i][7]);
        }
    }
}

// ---------------- launch ----------------
extern "C" void kernel_launch(void* const* d_in, const int* in_sizes, int n_in,
                              void* d_out, int out_size) {
    const float* node_feat = (const float*)d_in[0];
    const float* xyz = (const float*)d_in[1];
    const int* src = (const int*)d_in[2];
    const int* dst = (const int*)d_in[3];
    const float* ew1 = (const float*)d_in[4];
    const float* eb1 = (const float*)d_in[5];
    const float* ew2 = (const float*)d_in[6];
    const float* eb2 = (const float*)d_in[7];
    const float* cw1 = (const float*)d_in[8];
    const float* cb1 = (const float*)d_in[9];
    const float* cw2 = (const float*)d_in[10];
    const float* nw1 = (const float*)d_in[11];
    const float* nb1 = (const float*)d_in[12];
    const float* nw2 = (const float*)d_in[13];
    const float* nb2 = (const float*)d_in[14];
    const float* lng = (const float*)d_in[15];
    const float* lnb = (const float*)d_in[16];
    const float* ow  = (const float*)d_in[17];
    const float* ob  = (const float*)d_in[18];

    const int N = in_sizes[0] / C;
    const int E = in_sizes[2];

    float *hA, *hB, *xA, *hn, *xs, *Ps, *Pd;
    int *cnt, *cur, *off, *bsum, *perm;
    cudaGetSymbolAddress((void**)&hA, g_hA);
    cudaGetSymbolAddress((void**)&hB, g_hB);
    cudaGetSymbolAddress((void**)&xA, g_xA);
    cudaGetSymbolAddress((void**)&hn, g_hn);
    cudaGetSymbolAddress((void**)&xs, g_xs);
    cudaGetSymbolAddress((void**)&Ps, g_Ps);
    cudaGetSymbolAddress((void**)&Pd, g_Pd);
    cudaGetSymbolAddress((void**)&cnt, g_cnt);
    cudaGetSymbolAddress((void**)&cur, g_cur);
    cudaGetSymbolAddress((void**)&off, g_off);
    cudaGetSymbolAddress((void**)&bsum, g_bsum);
    cudaGetSymbolAddress((void**)&perm, g_perm);

    cudaFuncSetAttribute(pre_kernel,  cudaFuncAttributeMaxDynamicSharedMemorySize, PRE_SMEM_BYTES);
    cudaFuncSetAttribute(edge_kernel, cudaFuncAttributeMaxDynamicSharedMemorySize, EDGE_SMEM_BYTES);
    cudaFuncSetAttribute(node_kernel, cudaFuncAttributeMaxDynamicSharedMemorySize, NODE_SMEM_BYTES);
    cudaFuncSetAttribute(out_kernel,  cudaFuncAttributeMaxDynamicSharedMemorySize, OUT_SMEM_BYTES);

    const int ntiles_n = (N + TE - 1) / TE;
    const int ntiles_o = (N + OTILE - 1) / OTILE;
    const int nb = (N + SCB - 1) / SCB;

    // counting sort of edges by dst (reused by both layers)
    zero_int_kernel<<<(N + BT - 1) / BT, BT>>>(cnt, cur, N);
    hist_kernel<<<(E + BT - 1) / BT, BT>>>(dst, cnt, E);
    scan1_kernel<<<nb, 256>>>(cnt, off, bsum, N);
    scan2_kernel<<<1, 128>>>(bsum, nb);
    scatter_kernel<<<(E + BT - 1) / BT, BT>>>(dst, off, bsum, cur, perm, E);

    // layer 0
    pre_kernel<<<ntiles_n, BT, PRE_SMEM_BYTES>>>(node_feat, ew1, eb1, Ps, Pd, N);
    zero_kernel<<<512, BT>>>(hn, xs, N*C, N*4);
    edge_kernel<<<296, BT, EDGE_SMEM_BYTES>>>(Ps, Pd, ew1 + 128*C, xyz, src, dst, perm,
        ew2, eb2, cw1, cb1, cw2, hn, xs, E, 1);
    node_kernel<<<ntiles_n, BT, NODE_SMEM_BYTES>>>(node_feat, xyz, hn, xs, cnt,
        nw1, nb1, nw2, nb2, lng, lnb, hA, xA, N, 1);

    // layer 1 (coord path + x update dead w.r.t. output -> skipped)
    pre_kernel<<<ntiles_n, BT, PRE_SMEM_BYTES>>>(hA, ew1 + 129*C, eb1 + C, Ps, Pd, N);
    zero_kernel<<<512, BT>>>(hn, xs, N*C, 0);
    edge_kernel<<<296, BT, EDGE_SMEM_BYTES>>>(Ps, Pd, ew1 + 129*C + 128*C, xA, src, dst, perm,
        ew2 + C*C, eb2 + C, cw1 + C*C, cb1 + C, cw2 + C, hn, xs, E, 0);
    node_kernel<<<ntiles_n, BT, NODE_SMEM_BYTES>>>(hA, xA, hn, xs, cnt,
        nw1 + 2*C*C, nb1 + C, nw2 + C*C, nb2 + C, lng, lnb, hB, xA, N, 0);

    out_kernel<<<ntiles_o, BT, OUT_SMEM_BYTES>>>(hB, ow, ob, (float*)d_out, N);
}